// round 4
// baseline (speedup 1.0000x reference)
#include <cuda_runtime.h>
#include <math.h>

#define BB   8
#define NN   2048
#define KNB  32
#define FIN  256
#define FOUT 256
#define CC   512          // 2*FOUT
#define ROWS 16384        // BB*NN

#define TM   64           // rows per block in GEMM
#define KF   64           // f-chunk for W tile
#define NQ   64           // float4 quads per 256-f row
#define ASTR 65           // A-tile quad stride (padding -> conflict-free)

// ---------------- scratch (device globals; no allocation allowed) -------------
__device__ float g_WxT[FIN * FOUT];             // [f][o]
__device__ float g_WnT[FIN * FOUT];             // [f][o], pre-scaled by 1/32
__device__ float g_partials[256 * 1024];        // per-block [sum(512); sumsq(512)]
__device__ float g_scale[CC];
__device__ float g_shift[CC];

// ---------------- f32x2 helpers ----------------------------------------------
__device__ __forceinline__ unsigned long long pk2(float lo, float hi) {
    unsigned long long r;
    asm("mov.b64 %0, {%1, %2};" : "=l"(r) : "f"(lo), "f"(hi));
    return r;
}
__device__ __forceinline__ void fma2(unsigned long long& d,
                                     unsigned long long a,
                                     unsigned long long b) {
    asm("fma.rn.f32x2 %0, %1, %2, %0;" : "+l"(d) : "l"(a), "l"(b));
}
__device__ __forceinline__ float2 up2(unsigned long long v) {
    float lo, hi;
    asm("mov.b64 {%0, %1}, %2;" : "=f"(lo), "=f"(hi) : "l"(v));
    return make_float2(lo, hi);
}
__device__ __forceinline__ float cmp4(const float4& v, int ff) {
    return ff == 0 ? v.x : (ff == 1 ? v.y : (ff == 2 ? v.z : v.w));
}

// ---------------- k0: tiled transpose  out[C][R] = scale * in[R][C]^T ---------
__global__ void ktrans(const float* __restrict__ in, float* __restrict__ out,
                       int R, int C, float scale) {
    __shared__ float tile[32][33];
    int rb = blockIdx.y * 32, cb = blockIdx.x * 32;
    int tx = threadIdx.x, ty = threadIdx.y;
#pragma unroll
    for (int j = 0; j < 32; j += 8)
        tile[ty + j][tx] = in[(long long)(rb + ty + j) * C + cb + tx] * scale;
    __syncthreads();
#pragma unroll
    for (int j = 0; j < 32; j += 8)
        out[(long long)(cb + ty + j) * R + rb + tx] = tile[tx][ty + j];
}

// ---------------- k1: gather-mean phase + dual GEMM (serial phases) -----------
// grid (NN/TM, BB), 512 threads
// smem: xs4[64 fq][65 r-pad] | xm4[64 fq][65] | wt[64 f][256 o] | sIdx[2048]
__global__ __launch_bounds__(512, 1)
void k1_gemm(const float* __restrict__ x,
             const int* __restrict__ idx,
             const float* __restrict__ WxT, const float* __restrict__ Wxb,
             const float* __restrict__ WnT, const float* __restrict__ Wnb,
             float* __restrict__ out) {
    extern __shared__ float sm[];
    float4* xs4 = (float4*)sm;                         // 4160 quads (66560 B)
    float4* xm4 = (float4*)(sm + 16640);               // 4160 quads
    float*  wt  = sm + 33280;                          // 16384 floats (65536 B)
    int*    sIdx = (int*)(sm + 49664);                 // 2048 ints (8192 B)

    const int tid  = threadIdx.x;
    const int lane = tid & 31;
    const int gw   = tid >> 5;          // warp id 0..15
    const int b    = blockIdx.y;
    const int n0   = blockIdx.x * TM;
    const float4* Xb = (const float4*)(x + (size_t)b * NN * FIN);

    // ---- load idx tile ----
    {
        const int* src = idx + n0 * KNB;
        for (int i = tid; i < TM * KNB; i += 512) sIdx[i] = src[i];
    }
    // ---- load xs tile (coalesced LDG, conflict-free STS.128) ----
    for (int t = gw; t < 2 * TM; t += 16) {
        int r = t >> 1, half = t & 1;
        int fq = half * 32 + lane;
        xs4[fq * ASTR + r] = Xb[(size_t)(n0 + r) * NQ + fq];
    }
    __syncthreads();   // sIdx ready for gather

    // ---- gather phase: warp-per-4-rows, coalesced, register accumulation ----
    {
        const int rbase = gw * 4;
        float4 acc[4][2];
#pragma unroll
        for (int rr = 0; rr < 4; rr++) {
            acc[rr][0] = make_float4(0.f, 0.f, 0.f, 0.f);
            acc[rr][1] = make_float4(0.f, 0.f, 0.f, 0.f);
        }
#pragma unroll 2
        for (int k = 0; k < KNB; k++) {
#pragma unroll
            for (int rr = 0; rr < 4; rr++) {
                int nb = sIdx[(rbase + rr) * KNB + k];
                const float4* Xr = Xb + (size_t)nb * NQ;
                float4 v0 = Xr[lane];
                float4 v1 = Xr[lane + 32];
                acc[rr][0].x += v0.x; acc[rr][0].y += v0.y;
                acc[rr][0].z += v0.z; acc[rr][0].w += v0.w;
                acc[rr][1].x += v1.x; acc[rr][1].y += v1.y;
                acc[rr][1].z += v1.z; acc[rr][1].w += v1.w;
            }
        }
#pragma unroll
        for (int rr = 0; rr < 4; rr++) {
            xm4[lane        * ASTR + rbase + rr] = acc[rr][0];
            xm4[(lane + 32) * ASTR + rbase + rr] = acc[rr][1];
        }
    }
    __syncthreads();   // xm ready; sIdx dead

    const int rg = tid >> 6;          // 0..7  (8 rows each)
    const int cg = tid & 63;          // 0..63 (4 cols each)
    const int r0 = rg * 8;
    const int c0 = cg * 4;

#pragma unroll
    for (int pass = 0; pass < 2; pass++) {
        const float4* A4 = pass ? xm4 : xs4;
        const float*  WT = pass ? WnT : WxT;   // WnT pre-scaled by 1/32
        const float*  Wb = pass ? Wnb : Wxb;

        unsigned long long acc[16];   // [rowpair 0..3][col 0..3]
#pragma unroll
        for (int i = 0; i < 16; i++) acc[i] = 0ull;

        for (int kc = 0; kc < FIN; kc += KF) {
            __syncthreads();
            // load W chunk [KF][256] from pre-transposed WT (conflict-free)
            for (int i = tid; i < KF * (FOUT / 4); i += 512) {
                int f = i >> 6, oq = i & 63;
                float4 v = *(const float4*)(WT + (size_t)(kc + f) * FOUT + oq * 4);
                *(float4*)(wt + f * FOUT + oq * 4) = v;
            }
            __syncthreads();

#pragma unroll 4
            for (int fq8 = 0; fq8 < KF / 4; fq8++) {
                const int fq = (kc >> 2) + fq8;
                // A micro-tile: 8 rows x 4 f (broadcast LDS.128)
                float4 a0 = A4[fq * ASTR + r0 + 0];
                float4 a1 = A4[fq * ASTR + r0 + 1];
                float4 a2 = A4[fq * ASTR + r0 + 2];
                float4 a3 = A4[fq * ASTR + r0 + 3];
                float4 a4 = A4[fq * ASTR + r0 + 4];
                float4 a5 = A4[fq * ASTR + r0 + 5];
                float4 a6 = A4[fq * ASTR + r0 + 6];
                float4 a7 = A4[fq * ASTR + r0 + 7];
#pragma unroll
                for (int ff = 0; ff < 4; ff++) {
                    float4 bv = *(const float4*)(wt + (fq8 * 4 + ff) * FOUT + c0);
                    unsigned long long b0 = pk2(bv.x, bv.x);
                    unsigned long long b1 = pk2(bv.y, bv.y);
                    unsigned long long b2 = pk2(bv.z, bv.z);
                    unsigned long long b3 = pk2(bv.w, bv.w);
                    unsigned long long p0 = pk2(cmp4(a0, ff), cmp4(a1, ff));
                    unsigned long long p1 = pk2(cmp4(a2, ff), cmp4(a3, ff));
                    unsigned long long p2 = pk2(cmp4(a4, ff), cmp4(a5, ff));
                    unsigned long long p3 = pk2(cmp4(a6, ff), cmp4(a7, ff));
                    fma2(acc[0],  p0, b0); fma2(acc[1],  p0, b1);
                    fma2(acc[2],  p0, b2); fma2(acc[3],  p0, b3);
                    fma2(acc[4],  p1, b0); fma2(acc[5],  p1, b1);
                    fma2(acc[6],  p1, b2); fma2(acc[7],  p1, b3);
                    fma2(acc[8],  p2, b0); fma2(acc[9],  p2, b1);
                    fma2(acc[10], p2, b2); fma2(acc[11], p2, b3);
                    fma2(acc[12], p3, b0); fma2(acc[13], p3, b1);
                    fma2(acc[14], p3, b2); fma2(acc[15], p3, b3);
                }
            }
        }

        // epilogue: +bias, write raw h to out
        float4 bias = *(const float4*)(Wb + c0);
        float* obase = out + ((size_t)b * NN + n0 + r0) * CC + pass * FOUT + c0;
#pragma unroll
        for (int i = 0; i < 4; i++) {
            float2 p0 = up2(acc[i * 4 + 0]);
            float2 p1 = up2(acc[i * 4 + 1]);
            float2 p2 = up2(acc[i * 4 + 2]);
            float2 p3 = up2(acc[i * 4 + 3]);
            float4 lo = make_float4(p0.x + bias.x, p1.x + bias.y,
                                    p2.x + bias.z, p3.x + bias.w);
            float4 hi = make_float4(p0.y + bias.x, p1.y + bias.y,
                                    p2.y + bias.z, p3.y + bias.w);
            *(float4*)(obase + (size_t)(2 * i) * CC)     = lo;
            *(float4*)(obase + (size_t)(2 * i + 1) * CC) = hi;
        }
    }
}

// ---------------- k2: row L2-normalize + relu (in place) + channel partials ---
__global__ __launch_bounds__(256)
void k2_norm(float* __restrict__ h, float* __restrict__ partials) {
    __shared__ float sp[8 * 1024];
    const int tid  = threadIdx.x;
    const int w    = tid >> 5;
    const int lane = tid & 31;
    float s1[16], s2[16];
#pragma unroll
    for (int i = 0; i < 16; i++) { s1[i] = 0.f; s2[i] = 0.f; }

    const int row0 = blockIdx.x * 64 + w * 8;
    for (int rr = 0; rr < 8; rr++) {
        float* hr = h + (size_t)(row0 + rr) * CC;
        float4 v[4];
        float ss = 0.f;
#pragma unroll
        for (int c = 0; c < 4; c++) {
            v[c] = *(const float4*)(hr + c * 128 + lane * 4);
            ss += v[c].x * v[c].x + v[c].y * v[c].y
                + v[c].z * v[c].z + v[c].w * v[c].w;
        }
#pragma unroll
        for (int o = 16; o; o >>= 1) ss += __shfl_xor_sync(0xffffffffu, ss, o);
        float inv = 1.0f / fmaxf(sqrtf(ss), 1e-12f);
#pragma unroll
        for (int c = 0; c < 4; c++) {
            float4 t;
            t.x = fmaxf(v[c].x * inv, 0.f);
            t.y = fmaxf(v[c].y * inv, 0.f);
            t.z = fmaxf(v[c].z * inv, 0.f);
            t.w = fmaxf(v[c].w * inv, 0.f);
            *(float4*)(hr + c * 128 + lane * 4) = t;
            s1[c * 4 + 0] += t.x; s2[c * 4 + 0] += t.x * t.x;
            s1[c * 4 + 1] += t.y; s2[c * 4 + 1] += t.y * t.y;
            s1[c * 4 + 2] += t.z; s2[c * 4 + 2] += t.z * t.z;
            s1[c * 4 + 3] += t.w; s2[c * 4 + 3] += t.w * t.w;
        }
    }
#pragma unroll
    for (int c = 0; c < 4; c++) {
#pragma unroll
        for (int j = 0; j < 4; j++) {
            int ch = c * 128 + lane * 4 + j;
            sp[w * 1024 + ch]       = s1[c * 4 + j];
            sp[w * 1024 + 512 + ch] = s2[c * 4 + j];
        }
    }
    __syncthreads();
    for (int i = tid; i < 1024; i += 256) {
        float s = 0.f;
#pragma unroll
        for (int w2 = 0; w2 < 8; w2++) s += sp[w2 * 1024 + i];
        partials[(size_t)blockIdx.x * 1024 + i] = s;
    }
}

// ---------------- k3: reduce partials -> per-channel scale/shift --------------
__global__ void k3_stats(const float* __restrict__ partials,
                         const float* __restrict__ gamma,
                         const float* __restrict__ beta) {
    int ch   = blockIdx.x * 32 + (threadIdx.x >> 3);
    int part = threadIdx.x & 7;
    float s1 = 0.f, s2 = 0.f;
    for (int p = part; p < 256; p += 8) {
        s1 += partials[(size_t)p * 1024 + ch];
        s2 += partials[(size_t)p * 1024 + 512 + ch];
    }
#pragma unroll
    for (int o = 4; o; o >>= 1) {
        s1 += __shfl_xor_sync(0xffffffffu, s1, o);
        s2 += __shfl_xor_sync(0xffffffffu, s2, o);
    }
    if (part == 0) {
        const float invN = 1.0f / 16384.0f;
        float mu  = s1 * invN;
        float var = s2 * invN - mu * mu;
        float sc  = rsqrtf(var + 1e-5f) * gamma[ch];
        g_scale[ch] = sc;
        g_shift[ch] = beta[ch] - mu * sc;
    }
}

// ---------------- k4: apply BN elementwise (in place) -------------------------
__global__ __launch_bounds__(256)
void k4_bn(float* __restrict__ h) {
    int i  = blockIdx.x * 256 + threadIdx.x;     // float4 index
    int c0 = (i & 127) * 4;
    float4 v  = *((float4*)h + i);
    float4 sc = *(const float4*)(g_scale + c0);
    float4 sh = *(const float4*)(g_shift + c0);
    v.x = fmaf(v.x, sc.x, sh.x);
    v.y = fmaf(v.y, sc.y, sh.y);
    v.z = fmaf(v.z, sc.z, sh.z);
    v.w = fmaf(v.w, sc.w, sh.w);
    *((float4*)h + i) = v;
}

// ---------------- launch ------------------------------------------------------
extern "C" void kernel_launch(void* const* d_in, const int* in_sizes, int n_in,
                              void* d_out, int out_size) {
    const float* x     = (const float*)d_in[0];
    const int*   idx   = (const int*)d_in[1];
    const float* Wx_w  = (const float*)d_in[2];
    const float* Wx_b  = (const float*)d_in[3];
    const float* Wn_w  = (const float*)d_in[4];
    const float* Wn_b  = (const float*)d_in[5];
    const float* gamma = (const float*)d_in[6];
    const float* beta  = (const float*)d_in[7];
    float* out = (float*)d_out;

    float *WxT, *WnT, *parts;
    cudaGetSymbolAddress((void**)&WxT,   g_WxT);
    cudaGetSymbolAddress((void**)&WnT,   g_WnT);
    cudaGetSymbolAddress((void**)&parts, g_partials);

    dim3 tb(32, 8);
    // weight transposes: [o][f] -> [f][o]; 1/32 neighbor-mean folded into Wn
    ktrans<<<dim3(8, 8), tb>>>(Wx_w, WxT, 256, 256, 1.0f);
    ktrans<<<dim3(8, 8), tb>>>(Wn_w, WnT, 256, 256, 1.0f / 32.0f);

    const int smem = (16640 * 2 + 16384 + 2048) * 4;   // 206848 B
    cudaFuncSetAttribute(k1_gemm, cudaFuncAttributeMaxDynamicSharedMemorySize,
                         smem);
    k1_gemm<<<dim3(NN / TM, BB), 512, smem>>>(x, idx, WxT, Wx_b, WnT, Wn_b, out);
    k2_norm<<<256, 256>>>(out, parts);
    k3_stats<<<16, 256>>>(parts, gamma, beta);
    k4_bn<<<ROWS * CC / 4 / 256, 256>>>(out);
}

// round 9
// speedup vs baseline: 1.0204x; 1.0204x over previous
#include <cuda_runtime.h>
#include <math.h>

#define BB   8
#define NN   2048
#define KNB  32
#define FIN  256
#define FOUT 256
#define CC   512          // 2*FOUT
#define ROWS 16384        // BB*NN

#define TM   64           // rows per block
#define KF   32           // f-chunk for W tile
#define ASTR 65           // A-tile quad stride (padding)

// smem (floats): A4 [0,16640) | wt [16640,24832) | sIdx [24832,26880)
#define SMF_WT  16640
#define SMF_IDX 24832
#define SM_TOTAL (26880 * 4)   // 107520 B -> 2 CTAs/SM

// ---------------- scratch ----------------
__device__ float g_WxT[FIN * FOUT];             // [f][o]
__device__ float g_WnT[FIN * FOUT];             // [f][o], pre-scaled by 1/32
__device__ float g_partials[256 * 1024];
__device__ float g_scale[CC];
__device__ float g_shift[CC];

// ---------------- f32x2 helpers ----------------
__device__ __forceinline__ unsigned long long pk2(float lo, float hi) {
    unsigned long long r;
    asm("mov.b64 %0, {%1, %2};" : "=l"(r) : "f"(lo), "f"(hi));
    return r;
}
__device__ __forceinline__ void fma2(unsigned long long& d,
                                     unsigned long long a,
                                     unsigned long long b) {
    asm("fma.rn.f32x2 %0, %1, %2, %0;" : "+l"(d) : "l"(a), "l"(b));
}
__device__ __forceinline__ float2 up2(unsigned long long v) {
    float lo, hi;
    asm("mov.b64 {%0, %1}, %2;" : "=f"(lo), "=f"(hi) : "l"(v));
    return make_float2(lo, hi);
}
__device__ __forceinline__ float cmp4(const float4& v, int ff) {
    return ff == 0 ? v.x : (ff == 1 ? v.y : (ff == 2 ? v.z : v.w));
}

// ---------------- k0: tiled transpose (scale folded) --------------------------
__global__ void ktrans(const float* __restrict__ in, float* __restrict__ out,
                       int R, int C, float scale) {
    __shared__ float tile[32][33];
    int rb = blockIdx.y * 32, cb = blockIdx.x * 32;
    int tx = threadIdx.x, ty = threadIdx.y;
#pragma unroll
    for (int j = 0; j < 32; j += 8)
        tile[ty + j][tx] = in[(long long)(rb + ty + j) * C + cb + tx] * scale;
    __syncthreads();
#pragma unroll
    for (int j = 0; j < 32; j += 8)
        out[(long long)(cb + ty + j) * R + rb + tx] = tile[tx][ty + j];
}

// ---------------- k1: gather + dual GEMM, 256 thr, 2 CTAs/SM ------------------
__global__ __launch_bounds__(256, 2)
void k1_gemm(const float* __restrict__ x,
             const int* __restrict__ idx,
             const float* __restrict__ WxT, const float* __restrict__ Wxb,
             const float* __restrict__ WnT, const float* __restrict__ Wnb,
             float* __restrict__ out) {
    extern __shared__ float sm[];
    float4* A4  = (float4*)sm;                 // [64 fq][65 r-pad]
    float*  wt  = sm + SMF_WT;                 // [32 f][256 o]
    int*   sIdx = (int*)(sm + SMF_IDX);        // [64][32]

    const int tid  = threadIdx.x;
    const int lane = tid & 31;
    const int wid  = tid >> 5;                 // 0..7
    const int b    = blockIdx.y;
    const int n0   = blockIdx.x * TM;
    const float4* Xb = (const float4*)(x + (size_t)b * NN * FIN);

    // thread tile: warp = row-group (8 rows), lane = col-group (8 cols)
    const int r0 = wid * 8;
    const int c0 = lane * 8;

    // ---- idx tile ----
    for (int i = tid; i < TM * KNB; i += 256) sIdx[i] = idx[n0 * KNB + i];

    // ---- xs tile -> A4 ----
    for (int i = tid; i < TM * 64; i += 256) {
        int r = i >> 6, fq = i & 63;
        A4[fq * ASTR + r] = Xb[(size_t)(n0 + r) * 64 + fq];
    }
    __syncthreads();

#pragma unroll 1
    for (int pass = 0; pass < 2; pass++) {
        const float* WT = pass ? WnT : WxT;    // WnT pre-scaled by 1/32
        const float* Wb = pass ? Wnb : Wxb;

        unsigned long long acc[32];            // [rowpair 0..3][col 0..7]
#pragma unroll
        for (int i = 0; i < 32; i++) acc[i] = 0ull;

#pragma unroll 1
        for (int kc = 0; kc < FIN; kc += KF) {
            __syncthreads();
            for (int i = tid; i < KF * (FOUT / 4); i += 256) {
                int f = i >> 6, oq = i & 63;
                float4 v = *(const float4*)(WT + (size_t)(kc + f) * FOUT + oq * 4);
                *(float4*)(wt + f * FOUT + oq * 4) = v;
            }
            __syncthreads();

#pragma unroll 2
            for (int fq8 = 0; fq8 < KF / 4; fq8++) {
                const int fq = (kc >> 2) + fq8;
                float4 a0 = A4[fq * ASTR + r0 + 0];
                float4 a1 = A4[fq * ASTR + r0 + 1];
                float4 a2 = A4[fq * ASTR + r0 + 2];
                float4 a3 = A4[fq * ASTR + r0 + 3];
                float4 a4 = A4[fq * ASTR + r0 + 4];
                float4 a5 = A4[fq * ASTR + r0 + 5];
                float4 a6 = A4[fq * ASTR + r0 + 6];
                float4 a7 = A4[fq * ASTR + r0 + 7];
#pragma unroll
                for (int ff = 0; ff < 4; ff++) {
                    const float* wrow = wt + (fq8 * 4 + ff) * FOUT + c0;
                    float4 bv0 = *(const float4*)(wrow);
                    float4 bv1 = *(const float4*)(wrow + 4);
                    unsigned long long p0 = pk2(cmp4(a0, ff), cmp4(a1, ff));
                    unsigned long long p1 = pk2(cmp4(a2, ff), cmp4(a3, ff));
                    unsigned long long p2 = pk2(cmp4(a4, ff), cmp4(a5, ff));
                    unsigned long long p3 = pk2(cmp4(a6, ff), cmp4(a7, ff));
                    unsigned long long bb[8];
                    bb[0] = pk2(bv0.x, bv0.x); bb[1] = pk2(bv0.y, bv0.y);
                    bb[2] = pk2(bv0.z, bv0.z); bb[3] = pk2(bv0.w, bv0.w);
                    bb[4] = pk2(bv1.x, bv1.x); bb[5] = pk2(bv1.y, bv1.y);
                    bb[6] = pk2(bv1.z, bv1.z); bb[7] = pk2(bv1.w, bv1.w);
#pragma unroll
                    for (int c = 0; c < 8; c++) {
                        fma2(acc[c],      p0, bb[c]);
                        fma2(acc[8 + c],  p1, bb[c]);
                        fma2(acc[16 + c], p2, bb[c]);
                        fma2(acc[24 + c], p3, bb[c]);
                    }
                }
            }
        }

        // ---- epilogue: +bias, write h ----
        {
            float4 b0 = *(const float4*)(Wb + c0);
            float4 b1 = *(const float4*)(Wb + c0 + 4);
            float* obase = out + ((size_t)b * NN + n0 + r0) * CC
                         + pass * FOUT + c0;
#pragma unroll
            for (int i = 0; i < 4; i++) {
                float2 p[8];
#pragma unroll
                for (int c = 0; c < 8; c++) p[c] = up2(acc[i * 8 + c]);
                float4 lo0 = make_float4(p[0].x + b0.x, p[1].x + b0.y,
                                         p[2].x + b0.z, p[3].x + b0.w);
                float4 lo1 = make_float4(p[4].x + b1.x, p[5].x + b1.y,
                                         p[6].x + b1.z, p[7].x + b1.w);
                float4 hi0 = make_float4(p[0].y + b0.x, p[1].y + b0.y,
                                         p[2].y + b0.z, p[3].y + b0.w);
                float4 hi1 = make_float4(p[4].y + b1.x, p[5].y + b1.y,
                                         p[6].y + b1.z, p[7].y + b1.w);
                float* orow = obase + (size_t)(2 * i) * CC;
                *(float4*)(orow)          = lo0;
                *(float4*)(orow + 4)      = lo1;
                *(float4*)(orow + CC)     = hi0;
                *(float4*)(orow + CC + 4) = hi1;
            }
        }

        // ---- gather-mean into A tile (between passes only) ----
        if (pass == 0) {
            const int rbase = wid * 8;
            float4 g0[8], g1[8];
#pragma unroll
            for (int rr = 0; rr < 8; rr++) {
                g0[rr] = make_float4(0.f, 0.f, 0.f, 0.f);
                g1[rr] = make_float4(0.f, 0.f, 0.f, 0.f);
            }
            const int* ip = sIdx + rbase * KNB;
#pragma unroll 2
            for (int k = 0; k < KNB; k++) {
#pragma unroll
                for (int rr = 0; rr < 8; rr++) {
                    int nb = ip[rr * KNB + k];
                    const float4* Xr = Xb + (size_t)nb * 64;
                    float4 v0 = Xr[lane];
                    float4 v1 = Xr[lane + 32];
                    g0[rr].x += v0.x; g0[rr].y += v0.y;
                    g0[rr].z += v0.z; g0[rr].w += v0.w;
                    g1[rr].x += v1.x; g1[rr].y += v1.y;
                    g1[rr].z += v1.z; g1[rr].w += v1.w;
                }
            }
            __syncthreads();   // all warps done reading xs from A tile
#pragma unroll
            for (int rr = 0; rr < 8; rr++) {
                A4[lane        * ASTR + rbase + rr] = g0[rr];
                A4[(lane + 32) * ASTR + rbase + rr] = g1[rr];
            }
            // visibility handled by the sync at top of pass-1 chunk loop
        }
    }
}

// ---------------- k2: row L2-normalize + relu + channel partials --------------
__global__ __launch_bounds__(256)
void k2_norm(float* __restrict__ h, float* __restrict__ partials) {
    __shared__ float sp[8 * 1024];
    const int tid = threadIdx.x, w = tid >> 5, lane = tid & 31;
    float s1[16], s2[16];
#pragma unroll
    for (int i = 0; i < 16; i++) { s1[i] = 0.f; s2[i] = 0.f; }
    const int row0 = blockIdx.x * 64 + w * 8;
    for (int rr = 0; rr < 8; rr++) {
        float* hr = h + (size_t)(row0 + rr) * CC;
        float4 v[4];
        float ss = 0.f;
#pragma unroll
        for (int c = 0; c < 4; c++) {
            v[c] = *(const float4*)(hr + c * 128 + lane * 4);
            ss += v[c].x * v[c].x + v[c].y * v[c].y
                + v[c].z * v[c].z + v[c].w * v[c].w;
        }
#pragma unroll
        for (int o = 16; o; o >>= 1) ss += __shfl_xor_sync(0xffffffffu, ss, o);
        float inv = 1.0f / fmaxf(sqrtf(ss), 1e-12f);
#pragma unroll
        for (int c = 0; c < 4; c++) {
            float4 t;
            t.x = fmaxf(v[c].x * inv, 0.f);
            t.y = fmaxf(v[c].y * inv, 0.f);
            t.z = fmaxf(v[c].z * inv, 0.f);
            t.w = fmaxf(v[c].w * inv, 0.f);
            *(float4*)(hr + c * 128 + lane * 4) = t;
            s1[c * 4 + 0] += t.x; s2[c * 4 + 0] += t.x * t.x;
            s1[c * 4 + 1] += t.y; s2[c * 4 + 1] += t.y * t.y;
            s1[c * 4 + 2] += t.z; s2[c * 4 + 2] += t.z * t.z;
            s1[c * 4 + 3] += t.w; s2[c * 4 + 3] += t.w * t.w;
        }
    }
#pragma unroll
    for (int c = 0; c < 4; c++)
#pragma unroll
        for (int j = 0; j < 4; j++) {
            int ch = c * 128 + lane * 4 + j;
            sp[w * 1024 + ch]       = s1[c * 4 + j];
            sp[w * 1024 + 512 + ch] = s2[c * 4 + j];
        }
    __syncthreads();
    for (int i = tid; i < 1024; i += 256) {
        float s = 0.f;
#pragma unroll
        for (int w2 = 0; w2 < 8; w2++) s += sp[w2 * 1024 + i];
        partials[(size_t)blockIdx.x * 1024 + i] = s;
    }
}

// ---------------- k3: partials -> per-channel scale/shift ---------------------
__global__ void k3_stats(const float* __restrict__ partials,
                         const float* __restrict__ gamma,
                         const float* __restrict__ beta) {
    int ch = blockIdx.x * 32 + (threadIdx.x >> 3);
    int part = threadIdx.x & 7;
    float s1 = 0.f, s2 = 0.f;
    for (int p = part; p < 256; p += 8) {
        s1 += partials[(size_t)p * 1024 + ch];
        s2 += partials[(size_t)p * 1024 + 512 + ch];
    }
#pragma unroll
    for (int o = 4; o; o >>= 1) {
        s1 += __shfl_xor_sync(0xffffffffu, s1, o);
        s2 += __shfl_xor_sync(0xffffffffu, s2, o);
    }
    if (part == 0) {
        const float invN = 1.0f / 16384.0f;
        float mu = s1 * invN;
        float var = s2 * invN - mu * mu;
        float sc = rsqrtf(var + 1e-5f) * gamma[ch];
        g_scale[ch] = sc;
        g_shift[ch] = beta[ch] - mu * sc;
    }
}

// ---------------- k4: apply BN elementwise ------------------------------------
__global__ __launch_bounds__(256)
void k4_bn(float* __restrict__ h) {
    int i = blockIdx.x * 256 + threadIdx.x;
    int c0 = (i & 127) * 4;
    float4 v  = *((float4*)h + i);
    float4 sc = *(const float4*)(g_scale + c0);
    float4 sh = *(const float4*)(g_shift + c0);
    v.x = fmaf(v.x, sc.x, sh.x);
    v.y = fmaf(v.y, sc.y, sh.y);
    v.z = fmaf(v.z, sc.z, sh.z);
    v.w = fmaf(v.w, sc.w, sh.w);
    *((float4*)h + i) = v;
}

// ---------------- launch ------------------------------------------------------
extern "C" void kernel_launch(void* const* d_in, const int* in_sizes, int n_in,
                              void* d_out, int out_size) {
    const float* x     = (const float*)d_in[0];
    const int*   idx   = (const int*)d_in[1];
    const float* Wx_w  = (const float*)d_in[2];
    const float* Wx_b  = (const float*)d_in[3];
    const float* Wn_w  = (const float*)d_in[4];
    const float* Wn_b  = (const float*)d_in[5];
    const float* gamma = (const float*)d_in[6];
    const float* beta  = (const float*)d_in[7];
    float* out = (float*)d_out;

    float *WxT, *WnT, *parts;
    cudaGetSymbolAddress((void**)&WxT,   g_WxT);
    cudaGetSymbolAddress((void**)&WnT,   g_WnT);
    cudaGetSymbolAddress((void**)&parts, g_partials);

    dim3 tb(32, 8);
    ktrans<<<dim3(8, 8), tb>>>(Wx_w, WxT, 256, 256, 1.0f);
    ktrans<<<dim3(8, 8), tb>>>(Wn_w, WnT, 256, 256, 1.0f / 32.0f);

    cudaFuncSetAttribute(k1_gemm, cudaFuncAttributeMaxDynamicSharedMemorySize,
                         SM_TOTAL);
    k1_gemm<<<dim3(NN / TM, BB), 256, SM_TOTAL>>>(x, idx, WxT, Wx_b, WnT, Wn_b,
                                                  out);
    k2_norm<<<256, 256>>>(out, parts);
    k3_stats<<<16, 256>>>(parts, gamma, beta);
    k4_bn<<<ROWS * CC / 4 / 256, 256>>>(out);
}

// round 10
// speedup vs baseline: 1.5890x; 1.5571x over previous
#include <cuda_runtime.h>
#include <cuda_bf16.h>
#include <math.h>
#include <stdint.h>

#define BB   8
#define NN   2048
#define KNB  32
#define FIN  256
#define FOUT 256
#define CC   512
#define ROWS 16384
#define TM   64

// ---- smem layout (bytes) ----
#define SM_AH   0          // 64 rows x 528B  = 33792
#define SM_AL   33792      // -> 67584
#define SM_WH   67584      // 256 n x 48B = 12288 -> 79872
#define SM_WL   79872      // -> 92160
#define SM_BIAS 92160      // 512 f -> 94208
#define SM_IDX  94208      // 64*32*4 -> 102400
#define SM_TOTAL 102400
#define ASTRB 528          // A row stride bytes (264 bf16) -> conflict-free ldmatrix
#define WSTRB 48           // W row stride bytes (24 bf16)  -> conflict-free ldmatrix

// ---- device scratch ----
__device__ __align__(16) __nv_bfloat16 g_Whi[2 * FOUT * FIN];  // [mat][o][f]
__device__ __align__(16) __nv_bfloat16 g_Wlo[2 * FOUT * FIN];
__device__ float g_partials[256 * 1024];
__device__ float g_scale[CC];
__device__ float g_shift[CC];

// ---- PTX helpers ----
static __device__ __forceinline__ uint32_t smem_u32(const void* p) {
    uint32_t a;
    asm("{ .reg .u64 t; cvta.to.shared.u64 t, %1; cvt.u32.u64 %0, t; }"
        : "=r"(a) : "l"(p));
    return a;
}
#define LDSM4(r, a) \
    asm volatile("ldmatrix.sync.aligned.m8n8.x4.shared.b16 {%0,%1,%2,%3}, [%4];" \
        : "=r"((r)[0]), "=r"((r)[1]), "=r"((r)[2]), "=r"((r)[3]) : "r"(a))
#define LDSM2(r, a) \
    asm volatile("ldmatrix.sync.aligned.m8n8.x2.shared.b16 {%0,%1}, [%2];" \
        : "=r"((r)[0]), "=r"((r)[1]) : "r"(a))
#define MMA(d, a, bmat) \
    asm volatile("mma.sync.aligned.m16n8k16.row.col.f32.bf16.bf16.f32 " \
        "{%0,%1,%2,%3}, {%4,%5,%6,%7}, {%8,%9}, {%0,%1,%2,%3};" \
        : "+f"((d)[0]), "+f"((d)[1]), "+f"((d)[2]), "+f"((d)[3]) \
        : "r"((a)[0]), "r"((a)[1]), "r"((a)[2]), "r"((a)[3]), \
          "r"((bmat)[0]), "r"((bmat)[1]))

// ---- float4 -> bf16 hi/lo (4+4 elements, memory order preserved) ----
static __device__ __forceinline__ void cvtsplit(float4 v, uint2& h, uint2& l) {
    __nv_bfloat162 h0 = __floats2bfloat162_rn(v.x, v.y);
    __nv_bfloat162 h1 = __floats2bfloat162_rn(v.z, v.w);
    float2 f0 = __bfloat1622float2(h0);
    float2 f1 = __bfloat1622float2(h1);
    __nv_bfloat162 l0 = __floats2bfloat162_rn(v.x - f0.x, v.y - f0.y);
    __nv_bfloat162 l1 = __floats2bfloat162_rn(v.z - f1.x, v.w - f1.y);
    h = make_uint2(*(uint32_t*)&h0, *(uint32_t*)&h1);
    l = make_uint2(*(uint32_t*)&l0, *(uint32_t*)&l1);
}

// ---------------- k0: split W -> bf16 hi/lo (1/32 folded into Wn) -------------
__global__ void kwsplit(const float* __restrict__ Wx, const float* __restrict__ Wn) {
    int i = blockIdx.x * 256 + threadIdx.x;            // 0..131071
    float v = (i < 65536) ? Wx[i] : Wn[i - 65536] * (1.0f / 32.0f);
    __nv_bfloat16 h = __float2bfloat16(v);
    g_Whi[i] = h;
    g_Wlo[i] = __float2bfloat16(v - __bfloat162float(h));
}

// ---------------- k1: gather + dual GEMM on HMMA (mma.sync bf16 split) --------
// grid (NN/TM, BB) = (32, 8), 512 threads, 2 CTAs/SM -> all CTAs resident
__global__ __launch_bounds__(512, 2)
void k1_gemm(const float* __restrict__ x,
             const int* __restrict__ idx,
             const float* __restrict__ Wxb, const float* __restrict__ Wnb,
             float* __restrict__ out) {
    extern __shared__ char smem[];
    const uint32_t sb = smem_u32(smem);
    const int tid = threadIdx.x, lane = tid & 31, wid = tid >> 5;  // 16 warps
    const int b = blockIdx.y, n0 = blockIdx.x * TM;
    const float4* Xb = (const float4*)(x + (size_t)b * NN * FIN);

    const int wm = wid >> 2;          // m-stripe 0..3 (16 rows)
    const int wn = wid & 3;           // n-quarter 0..3 (64 cols)
    const int g  = lane >> 2, tg = lane & 3;

    // ---- bias + idx -> smem ----
    ((float*)(smem + SM_BIAS))[tid] = (tid < 256) ? Wxb[tid] : Wnb[tid - 256];
    int* sIdx = (int*)(smem + SM_IDX);
    for (int i = tid; i < TM * KNB; i += 512) sIdx[i] = idx[n0 * KNB + i];

    // ---- xs -> A tile (bf16 hi/lo) ----
    for (int i = tid; i < TM * 64; i += 512) {
        int r = i >> 6, kq = i & 63;
        uint2 h, l;
        cvtsplit(Xb[(size_t)(n0 + r) * 64 + kq], h, l);
        *(uint2*)(smem + SM_AH + r * ASTRB + kq * 8) = h;
        *(uint2*)(smem + SM_AL + r * ASTRB + kq * 8) = l;
    }
    __syncthreads();

    // fragment addresses (per lane)
    const uint32_t a_row = (uint32_t)(wm * 16 + (lane & 7) + ((lane >> 3) & 1) * 8);
    const uint32_t a_kb  = (uint32_t)(((lane >> 4) & 1) * 16);   // bytes
    const uint32_t ah_base = sb + SM_AH + a_row * ASTRB + a_kb;
    const uint32_t al_base = sb + SM_AL + a_row * ASTRB + a_kb;
    const int lb = lane & 15;
    const uint32_t b_row = (uint32_t)(wn * 64 + (lb & 7));
    const uint32_t b_kb  = (uint32_t)(((lb >> 3) & 1) * 16);
    const uint32_t wh_base = sb + SM_WH + b_row * WSTRB + b_kb;
    const uint32_t wl_base = sb + SM_WL + b_row * WSTRB + b_kb;

#pragma unroll 1
    for (int pass = 0; pass < 2; pass++) {
        float acc[8][4];
#pragma unroll
        for (int nt = 0; nt < 8; nt++)
#pragma unroll
            for (int j = 0; j < 4; j++) acc[nt][j] = 0.f;

        const __nv_bfloat16* WHsrc = g_Whi + pass * 65536;
        const __nv_bfloat16* WLsrc = g_Wlo + pass * 65536;

#pragma unroll 1
        for (int c = 0; c < 16; c++) {          // K chunks of 16
            __syncthreads();
            // load W chunk [256 n][16 k] hi/lo -> padded smem
            for (int t = tid; t < 2048; t += 512) {
                int hl = t >> 10, e = t & 1023;
                int n = e >> 2, q = e & 3;
                const __nv_bfloat16* src = hl ? WLsrc : WHsrc;
                uint2 v = *(const uint2*)(src + n * 256 + c * 16 + q * 4);
                *(uint2*)(smem + (hl ? SM_WL : SM_WH) + n * WSTRB + q * 8) = v;
            }
            __syncthreads();

            uint32_t ah[4], al[4];
            LDSM4(ah, ah_base + c * 32);
            LDSM4(al, al_base + c * 32);
#pragma unroll
            for (int nt = 0; nt < 8; nt++) {
                uint32_t bh[2], bl[2];
                LDSM2(bh, wh_base + (uint32_t)(nt * 8) * WSTRB);
                LDSM2(bl, wl_base + (uint32_t)(nt * 8) * WSTRB);
                MMA(acc[nt], ah, bh);
                MMA(acc[nt], ah, bl);
                MMA(acc[nt], al, bh);
            }
        }

        // ---- epilogue: +bias, write h (registers -> gmem) ----
        {
            const float* sbias = (const float*)(smem + SM_BIAS) + pass * 256 + wn * 64;
            float* ob = out + ((size_t)b * NN + n0 + wm * 16) * CC
                      + pass * 256 + wn * 64;
#pragma unroll
            for (int nt = 0; nt < 8; nt++) {
                int col = nt * 8 + 2 * tg;
                float2 bv = *(const float2*)(sbias + col);
                float2 lo = make_float2(acc[nt][0] + bv.x, acc[nt][1] + bv.y);
                float2 hi = make_float2(acc[nt][2] + bv.x, acc[nt][3] + bv.y);
                *(float2*)(ob + (size_t)g * CC + col)       = lo;
                *(float2*)(ob + (size_t)(g + 8) * CC + col) = hi;
            }
        }

        // ---- gather-mean -> A tile (between passes) ----
        if (pass == 0) {
            const int rbase = wid * 4;
            float4 g0[4], g1[4];
#pragma unroll
            for (int rr = 0; rr < 4; rr++) {
                g0[rr] = make_float4(0.f, 0.f, 0.f, 0.f);
                g1[rr] = make_float4(0.f, 0.f, 0.f, 0.f);
            }
            const int* ip = sIdx + rbase * KNB;
#pragma unroll 2
            for (int k = 0; k < KNB; k++) {
#pragma unroll
                for (int rr = 0; rr < 4; rr++) {
                    int nb = ip[rr * KNB + k];
                    const float4* Xr = Xb + (size_t)nb * 64;
                    float4 v0 = Xr[lane];
                    float4 v1 = Xr[lane + 32];
                    g0[rr].x += v0.x; g0[rr].y += v0.y;
                    g0[rr].z += v0.z; g0[rr].w += v0.w;
                    g1[rr].x += v1.x; g1[rr].y += v1.y;
                    g1[rr].z += v1.z; g1[rr].w += v1.w;
                }
            }
            __syncthreads();   // all warps finished pass-0 MMAs on A tile
#pragma unroll
            for (int rr = 0; rr < 4; rr++) {
                uint2 h, l;
                cvtsplit(g0[rr], h, l);
                *(uint2*)(smem + SM_AH + (rbase + rr) * ASTRB + lane * 8) = h;
                *(uint2*)(smem + SM_AL + (rbase + rr) * ASTRB + lane * 8) = l;
                cvtsplit(g1[rr], h, l);
                *(uint2*)(smem + SM_AH + (rbase + rr) * ASTRB + (lane + 32) * 8) = h;
                *(uint2*)(smem + SM_AL + (rbase + rr) * ASTRB + (lane + 32) * 8) = l;
            }
            // visibility: first sync inside pass-1 chunk loop
        }
    }
}

// ---------------- k2: row L2-normalize + relu + channel partials --------------
__global__ __launch_bounds__(256)
void k2_norm(float* __restrict__ h, float* __restrict__ partials) {
    __shared__ float sp[8 * 1024];
    const int tid = threadIdx.x, w = tid >> 5, lane = tid & 31;
    float s1[16], s2[16];
#pragma unroll
    for (int i = 0; i < 16; i++) { s1[i] = 0.f; s2[i] = 0.f; }
    const int row0 = blockIdx.x * 64 + w * 8;
    for (int rr = 0; rr < 8; rr++) {
        float* hr = h + (size_t)(row0 + rr) * CC;
        float4 v[4];
        float ss = 0.f;
#pragma unroll
        for (int c = 0; c < 4; c++) {
            v[c] = *(const float4*)(hr + c * 128 + lane * 4);
            ss += v[c].x * v[c].x + v[c].y * v[c].y
                + v[c].z * v[c].z + v[c].w * v[c].w;
        }
#pragma unroll
        for (int o = 16; o; o >>= 1) ss += __shfl_xor_sync(0xffffffffu, ss, o);
        float inv = 1.0f / fmaxf(sqrtf(ss), 1e-12f);
#pragma unroll
        for (int c = 0; c < 4; c++) {
            float4 t;
            t.x = fmaxf(v[c].x * inv, 0.f);
            t.y = fmaxf(v[c].y * inv, 0.f);
            t.z = fmaxf(v[c].z * inv, 0.f);
            t.w = fmaxf(v[c].w * inv, 0.f);
            *(float4*)(hr + c * 128 + lane * 4) = t;
            s1[c * 4 + 0] += t.x; s2[c * 4 + 0] += t.x * t.x;
            s1[c * 4 + 1] += t.y; s2[c * 4 + 1] += t.y * t.y;
            s1[c * 4 + 2] += t.z; s2[c * 4 + 2] += t.z * t.z;
            s1[c * 4 + 3] += t.w; s2[c * 4 + 3] += t.w * t.w;
        }
    }
#pragma unroll
    for (int c = 0; c < 4; c++)
#pragma unroll
        for (int j = 0; j < 4; j++) {
            int ch = c * 128 + lane * 4 + j;
            sp[w * 1024 + ch]       = s1[c * 4 + j];
            sp[w * 1024 + 512 + ch] = s2[c * 4 + j];
        }
    __syncthreads();
    for (int i = tid; i < 1024; i += 256) {
        float s = 0.f;
#pragma unroll
        for (int w2 = 0; w2 < 8; w2++) s += sp[w2 * 1024 + i];
        partials[(size_t)blockIdx.x * 1024 + i] = s;
    }
}

// ---------------- k3: partials -> per-channel scale/shift ---------------------
__global__ void k3_stats(const float* __restrict__ partials,
                         const float* __restrict__ gamma,
                         const float* __restrict__ beta) {
    int ch = blockIdx.x * 32 + (threadIdx.x >> 3);
    int part = threadIdx.x & 7;
    float s1 = 0.f, s2 = 0.f;
    for (int p = part; p < 256; p += 8) {
        s1 += partials[(size_t)p * 1024 + ch];
        s2 += partials[(size_t)p * 1024 + 512 + ch];
    }
#pragma unroll
    for (int o = 4; o; o >>= 1) {
        s1 += __shfl_xor_sync(0xffffffffu, s1, o);
        s2 += __shfl_xor_sync(0xffffffffu, s2, o);
    }
    if (part == 0) {
        const float invN = 1.0f / 16384.0f;
        float mu = s1 * invN;
        float var = s2 * invN - mu * mu;
        float sc = rsqrtf(var + 1e-5f) * gamma[ch];
        g_scale[ch] = sc;
        g_shift[ch] = beta[ch] - mu * sc;
    }
}

// ---------------- k4: apply BN elementwise ------------------------------------
__global__ __launch_bounds__(256)
void k4_bn(float* __restrict__ h) {
    int i = blockIdx.x * 256 + threadIdx.x;
    int c0 = (i & 127) * 4;
    float4 v  = *((float4*)h + i);
    float4 sc = *(const float4*)(g_scale + c0);
    float4 sh = *(const float4*)(g_shift + c0);
    v.x = fmaf(v.x, sc.x, sh.x);
    v.y = fmaf(v.y, sc.y, sh.y);
    v.z = fmaf(v.z, sc.z, sh.z);
    v.w = fmaf(v.w, sc.w, sh.w);
    *((float4*)h + i) = v;
}

// ---------------- launch ------------------------------------------------------
extern "C" void kernel_launch(void* const* d_in, const int* in_sizes, int n_in,
                              void* d_out, int out_size) {
    const float* x     = (const float*)d_in[0];
    const int*   idx   = (const int*)d_in[1];
    const float* Wx_w  = (const float*)d_in[2];
    const float* Wx_b  = (const float*)d_in[3];
    const float* Wn_w  = (const float*)d_in[4];
    const float* Wn_b  = (const float*)d_in[5];
    const float* gamma = (const float*)d_in[6];
    const float* beta  = (const float*)d_in[7];
    float* out = (float*)d_out;

    float* parts;
    cudaGetSymbolAddress((void**)&parts, g_partials);

    kwsplit<<<512, 256>>>(Wx_w, Wn_w);

    cudaFuncSetAttribute(k1_gemm, cudaFuncAttributeMaxDynamicSharedMemorySize,
                         SM_TOTAL);
    k1_gemm<<<dim3(NN / TM, BB), 512, SM_TOTAL>>>(x, idx, Wx_b, Wn_b, out);
    k2_norm<<<256, 256>>>(out, parts);
    k3_stats<<<16, 256>>>(parts, gamma, beta);
    k4_bn<<<ROWS * CC / 4 / 256, 256>>>(out);
}